// round 1
// baseline (speedup 1.0000x reference)
#include <cuda_runtime.h>
#include <cstdint>

// Problem constants: B=4, T=1024, E=4, C=512, i=512, IN=2048, OUT=8192
#define BM 128
#define BN 128
#define BK 32

// Scratch (allocation-free rule: __device__ globals)
static __device__ float g_Xd[4ull * 4 * 512 * 512];        // (B,E,C,i)     16 MB
static __device__ float g_Y [4ull * 4 * 512 * 8192];       // (B,E,C,OUT)  256 MB
static __device__ float g_S [4 * 1024];                    // (B,T) combine row sums

__device__ __forceinline__ uint32_t f2tf(float f) {
    uint32_t u;
    asm("cvt.rna.tf32.f32 %0, %1;" : "=r"(u) : "f"(f));
    return u;
}

// S[b,t] = sum_{e,c} combine[b,t,e,c]  (2048 contiguous floats per row)
__global__ void combine_rowsum(const float* __restrict__ cmb, float* __restrict__ S) {
    int row = blockIdx.x * (blockDim.x >> 5) + (threadIdx.x >> 5);
    int lane = threadIdx.x & 31;
    const float4* p = reinterpret_cast<const float4*>(cmb + (size_t)row * 2048);
    float s = 0.f;
    #pragma unroll 4
    for (int j = lane; j < 512; j += 32) {
        float4 v = p[j];
        s += (v.x + v.y) + (v.z + v.w);
    }
    #pragma unroll
    for (int o = 16; o; o >>= 1) s += __shfl_xor_sync(0xffffffffu, s, o);
    if (lane == 0) S[row] = s;
}

// Generic batched tf32 GEMM: C[M,N] = A @ B.
//   A_MK: A stored (m,k) with k contiguous (else (k,m) with m contiguous)
//   B_NK: B stored (n,k) with k contiguous (else (k,n) with n contiguous)
// Exact-tile: M,N multiples of 128, K multiple of 32 (true for all 3 stages).
template <bool A_MK, bool B_NK, bool HAS_BIAS>
__global__ void __launch_bounds__(256, 2) gemm_tf32(
    const float* __restrict__ Ag, const float* __restrict__ Bg, float* __restrict__ Cg,
    int K, long long lda, long long ldb, long long ldc,
    long long aOut, long long aIn, long long bOut, long long bIn,
    long long cOut, long long cIn, int innerCount,
    const float* __restrict__ bias, const float* __restrict__ Svec, long long sOut)
{
    constexpr int A_PITCH = A_MK ? (BK + 4) : (BM + 8);
    constexpr int B_PITCH = B_NK ? (BK + 4) : (BN + 8);
    constexpr int A_WORDS = A_MK ? BM * (BK + 4) : BK * (BM + 8);
    constexpr int B_WORDS = B_NK ? BN * (BK + 4) : BK * (BN + 8);
    __shared__ uint32_t sA[A_WORDS];
    __shared__ uint32_t sB[B_WORDS];

    const int z  = blockIdx.z;
    const int zo = z / innerCount;
    const int zi = z - zo * innerCount;
    const float* A = Ag + (long long)zo * aOut + (long long)zi * aIn;
    const float* B = Bg + (long long)zo * bOut + (long long)zi * bIn;
    float*       C = Cg + (long long)zo * cOut + (long long)zi * cIn;

    const int m0g = blockIdx.y * BM;
    const int n0g = blockIdx.x * BN;
    const int tid  = threadIdx.x;
    const int warp = tid >> 5;
    const int lane = tid & 31;
    const int wm = warp & 3;   // 4 warps along M -> 32 rows each
    const int wn = warp >> 2;  // 2 warps along N -> 64 cols each
    const int g  = lane >> 2;
    const int tg = lane & 3;

    float acc[2][8][4];
    #pragma unroll
    for (int mi = 0; mi < 2; mi++)
        #pragma unroll
        for (int ni = 0; ni < 8; ni++)
            #pragma unroll
            for (int q = 0; q < 4; q++) acc[mi][ni][q] = 0.f;

    for (int k0g = 0; k0g < K; k0g += BK) {
        // ---- global -> smem (convert to tf32 on the way in) ----
        if constexpr (!A_MK) {   // A[(k)*lda + m], m contiguous
            #pragma unroll
            for (int j = 0; j < 4; j++) {
                int idx = tid + j * 256;
                int k = idx >> 5, m = (idx & 31) << 2;
                float4 v = *reinterpret_cast<const float4*>(&A[(long long)(k0g + k) * lda + m0g + m]);
                uint4 w = make_uint4(f2tf(v.x), f2tf(v.y), f2tf(v.z), f2tf(v.w));
                *reinterpret_cast<uint4*>(&sA[k * A_PITCH + m]) = w;
            }
        } else {                 // A[(m)*lda + k], k contiguous
            #pragma unroll
            for (int j = 0; j < 4; j++) {
                int idx = tid + j * 256;
                int m = idx >> 3, k = (idx & 7) << 2;
                float4 v = *reinterpret_cast<const float4*>(&A[(long long)(m0g + m) * lda + k0g + k]);
                uint4 w = make_uint4(f2tf(v.x), f2tf(v.y), f2tf(v.z), f2tf(v.w));
                *reinterpret_cast<uint4*>(&sA[m * A_PITCH + k]) = w;
            }
        }
        if constexpr (!B_NK) {   // B[(k)*ldb + n], n contiguous
            #pragma unroll
            for (int j = 0; j < 4; j++) {
                int idx = tid + j * 256;
                int k = idx >> 5, n = (idx & 31) << 2;
                float4 v = *reinterpret_cast<const float4*>(&B[(long long)(k0g + k) * ldb + n0g + n]);
                uint4 w = make_uint4(f2tf(v.x), f2tf(v.y), f2tf(v.z), f2tf(v.w));
                *reinterpret_cast<uint4*>(&sB[k * B_PITCH + n]) = w;
            }
        } else {                 // B[(n)*ldb + k], k contiguous
            #pragma unroll
            for (int j = 0; j < 4; j++) {
                int idx = tid + j * 256;
                int n = idx >> 3, k = (idx & 7) << 2;
                float4 v = *reinterpret_cast<const float4*>(&B[(long long)(n0g + n) * ldb + k0g + k]);
                uint4 w = make_uint4(f2tf(v.x), f2tf(v.y), f2tf(v.z), f2tf(v.w));
                *reinterpret_cast<uint4*>(&sB[n * B_PITCH + k]) = w;
            }
        }
        __syncthreads();

        #pragma unroll
        for (int ks = 0; ks < BK / 8; ks++) {
            const int k0 = ks * 8;
            uint32_t af[2][4], bf[8][2];
            #pragma unroll
            for (int mi = 0; mi < 2; mi++) {
                const int rb = wm * 32 + mi * 16;
                if constexpr (A_MK) {
                    af[mi][0] = sA[(rb + g)     * A_PITCH + k0 + tg];
                    af[mi][1] = sA[(rb + 8 + g) * A_PITCH + k0 + tg];
                    af[mi][2] = sA[(rb + g)     * A_PITCH + k0 + 4 + tg];
                    af[mi][3] = sA[(rb + 8 + g) * A_PITCH + k0 + 4 + tg];
                } else {
                    af[mi][0] = sA[(k0 + tg)     * A_PITCH + rb + g];
                    af[mi][1] = sA[(k0 + tg)     * A_PITCH + rb + 8 + g];
                    af[mi][2] = sA[(k0 + 4 + tg) * A_PITCH + rb + g];
                    af[mi][3] = sA[(k0 + 4 + tg) * A_PITCH + rb + 8 + g];
                }
            }
            #pragma unroll
            for (int ni = 0; ni < 8; ni++) {
                const int cb = wn * 64 + ni * 8 + g;
                if constexpr (B_NK) {
                    bf[ni][0] = sB[cb * B_PITCH + k0 + tg];
                    bf[ni][1] = sB[cb * B_PITCH + k0 + 4 + tg];
                } else {
                    bf[ni][0] = sB[(k0 + tg)     * B_PITCH + cb];
                    bf[ni][1] = sB[(k0 + 4 + tg) * B_PITCH + cb];
                }
            }
            #pragma unroll
            for (int mi = 0; mi < 2; mi++)
                #pragma unroll
                for (int ni = 0; ni < 8; ni++)
                    asm volatile(
                        "mma.sync.aligned.m16n8k8.row.col.f32.tf32.tf32.f32 "
                        "{%0,%1,%2,%3}, {%4,%5,%6,%7}, {%8,%9}, {%0,%1,%2,%3};\n"
                        : "+f"(acc[mi][ni][0]), "+f"(acc[mi][ni][1]),
                          "+f"(acc[mi][ni][2]), "+f"(acc[mi][ni][3])
                        : "r"(af[mi][0]), "r"(af[mi][1]), "r"(af[mi][2]), "r"(af[mi][3]),
                          "r"(bf[ni][0]), "r"(bf[ni][1]));
        }
        __syncthreads();
    }

    // ---- epilogue (optional rank-1 bias term: C += bias[n] * S[m]) ----
    const float* Sv = HAS_BIAS ? (Svec + (long long)zo * sOut) : nullptr;
    #pragma unroll
    for (int mi = 0; mi < 2; mi++) {
        const int r0 = m0g + wm * 32 + mi * 16 + g;
        float s0 = 0.f, s1 = 0.f;
        if constexpr (HAS_BIAS) { s0 = Sv[r0]; s1 = Sv[r0 + 8]; }
        #pragma unroll
        for (int ni = 0; ni < 8; ni++) {
            const int c0 = n0g + wn * 64 + ni * 8 + tg * 2;
            float2 v0 = make_float2(acc[mi][ni][0], acc[mi][ni][1]);
            float2 v1 = make_float2(acc[mi][ni][2], acc[mi][ni][3]);
            if constexpr (HAS_BIAS) {
                const float b0 = bias[c0], b1 = bias[c0 + 1];
                v0.x += b0 * s0; v0.y += b1 * s0;
                v1.x += b0 * s1; v1.y += b1 * s1;
            }
            *reinterpret_cast<float2*>(&C[(long long)r0 * ldc + c0]) = v0;
            *reinterpret_cast<float2*>(&C[(long long)(r0 + 8) * ldc + c0]) = v1;
        }
    }
}

extern "C" void kernel_launch(void* const* d_in, const int* in_sizes, int n_in,
                              void* d_out, int out_size)
{
    const float* x      = (const float*)d_in[0];  // (4,1024,2048)
    const float* cmb    = (const float*)d_in[1];  // (4,1024,4,512)
    const float* mask   = (const float*)d_in[2];  // (4,1024,4,512)
    const float* weight = (const float*)d_in[3];  // (8192,2048) == (4,8192,512) flat
    const float* bias   = (const float*)d_in[4];  // (8192,)
    float* out = (float*)d_out;                   // (4,1024,8192)

    float *Xd, *Y, *S;
    cudaGetSymbolAddress((void**)&Xd, g_Xd);
    cudaGetSymbolAddress((void**)&Y,  g_Y);
    cudaGetSymbolAddress((void**)&S,  g_S);

    // S[b,t] = sum_{e,c} combine
    combine_rowsum<<<512, 256>>>(cmb, S);

    // Stage 1: per (b,e)  Xd(512x512) = mask^T(512x1024) @ X(1024x512)
    //   A = mask[b,:,e,:]  layout (k=t, m=c) m-contig  -> A_MK=false, lda=2048
    //   B = x[b,:,e*512:]  layout (k=t, n=i) n-contig  -> B_NK=false, ldb=2048
    {
        dim3 grid(512 / BN, 512 / BM, 16);
        gemm_tf32<false, false, false><<<grid, 256>>>(
            mask, x, Xd,
            /*K*/1024, /*lda*/2048, /*ldb*/2048, /*ldc*/512,
            /*aOut(b)*/2097152LL, /*aIn(e)*/512LL,
            /*bOut(b)*/2097152LL, /*bIn(e)*/512LL,
            /*cOut(b)*/1048576LL, /*cIn(e)*/262144LL, /*inner*/4,
            nullptr, nullptr, 0);
    }

    // Stage 2: per (b,e)  Y(512x8192) = Xd(512x512) @ W[e]^T
    //   A = Xd[b,e]   (m=c,k=i) k-contig -> A_MK=true,  lda=512
    //   B = weight[e] (n=o,k=i) k-contig -> B_NK=true,  ldb=512
    {
        dim3 grid(8192 / BN, 512 / BM, 16);
        gemm_tf32<true, true, false><<<grid, 256>>>(
            Xd, weight, Y,
            /*K*/512, /*lda*/512, /*ldb*/512, /*ldc*/8192,
            /*aOut*/1048576LL, /*aIn*/262144LL,
            /*bOut*/0LL,       /*bIn*/4194304LL,
            /*cOut*/16777216LL, /*cIn*/4194304LL, /*inner*/4,
            nullptr, nullptr, 0);
    }

    // Stage 3: per b  Out(1024x8192) = Cmb(1024x2048) @ Yflat(2048x8192) + bias⊗S
    //   A = combine[b] (m=t,k=ec) k-contig -> A_MK=true,  lda=2048
    //   B = Y[b]       (k=ec,n=o) n-contig -> B_NK=false, ldb=8192
    {
        dim3 grid(8192 / BN, 1024 / BM, 4);
        gemm_tf32<true, false, true><<<grid, 256>>>(
            cmb, Y, out,
            /*K*/2048, /*lda*/2048, /*ldb*/8192, /*ldc*/8192,
            /*aOut*/2097152LL,  /*aIn*/0LL,
            /*bOut*/16777216LL, /*bIn*/0LL,
            /*cOut*/8388608LL,  /*cIn*/0LL, /*inner*/1,
            bias, S, /*sOut*/1024LL);
    }
}

// round 6
// speedup vs baseline: 1.5056x; 1.5056x over previous
#include <cuda_runtime.h>
#include <cstdint>
#include <cstddef>

// Problem: B=4, T=1024, E=4, C=512, i=512, IN=2048, OUT=8192
//   w[e,o,j] = weight_flat[e*4194304 + o*512 + j]   (torch-style reshape!)
//   Xd[b,e] = mask[b,:,e,:]^T @ x[b,:,e*512:]        (16x 512x512x1024)
//   Z[b,:,e*512:] = cmb[b,:,e,:] @ Xd[b,e]           (16x 1024x512x512)
//   out[b] = Z[b] @ Wr^T + bias (x) rowsum(cmb)      (M=4096,N=8192,K=2048)
//   with Wr[o, e*512+j] = tf32(w[e,o,j])  (permute + round fused)

// ---------------- scratch (allocation-free rule) ----------------
static __device__ float g_Xd[4ull * 4 * 512 * 512];    // 16 MB
static __device__ float g_Z [4096ull * 2048];          // 32 MB (tf32-rounded)
static __device__ float g_Wr[8192ull * 2048];          // 64 MB (permuted+rounded weight)
static __device__ float g_S [4 * 1024];

__device__ __forceinline__ uint32_t f2tf(float f) {
    uint32_t u;
    asm("cvt.rna.tf32.f32 %0, %1;" : "=r"(u) : "f"(f));
    return u;
}

// ---------------- tiny kernels ----------------
__global__ void combine_rowsum(const float* __restrict__ cmb, float* __restrict__ S) {
    int row = blockIdx.x * (blockDim.x >> 5) + (threadIdx.x >> 5);
    int lane = threadIdx.x & 31;
    const float4* p = reinterpret_cast<const float4*>(cmb + (size_t)row * 2048);
    float s = 0.f;
    #pragma unroll 4
    for (int j = lane; j < 512; j += 32) {
        float4 v = p[j];
        s += (v.x + v.y) + (v.z + v.w);
    }
    #pragma unroll
    for (int o = 16; o; o >>= 1) s += __shfl_xor_sync(0xffffffffu, s, o);
    if (lane == 0) S[row] = s;
}

// Wr[o, e*512 + j] = tf32(weight_flat[e*4194304 + o*512 + j]); 4 floats per thread.
__global__ void permute_round_w(const float* __restrict__ in, float* __restrict__ out) {
    size_t idx = (size_t)blockIdx.x * blockDim.x + threadIdx.x;  // 4,194,304 threads
    int j4 = (int)(idx & 127);          // 128 chunks of 4 along j
    int o  = (int)((idx >> 7) & 8191);
    int e  = (int)(idx >> 20);
    float4 v = *reinterpret_cast<const float4*>(in + (size_t)e * 4194304 + (size_t)o * 512 + j4 * 4);
    uint4 w = make_uint4(f2tf(v.x), f2tf(v.y), f2tf(v.z), f2tf(v.w));
    *reinterpret_cast<uint4*>(out + (size_t)o * 2048 + e * 512 + j4 * 4) = w;
}

// ---------------- SIMT tf32 GEMM (stages 1 & 2, small) ----------------
#define BM 128
#define BN 128
#define BK 32

template <bool A_MK, bool B_NK, bool ROUND_OUT>
__global__ void __launch_bounds__(256, 2) gemm_tf32(
    const float* __restrict__ Ag, const float* __restrict__ Bg, float* __restrict__ Cg,
    int K, long long lda, long long ldb, long long ldc,
    long long aOut, long long aIn, long long bOut, long long bIn,
    long long cOut, long long cIn, int innerCount)
{
    constexpr int A_PITCH = A_MK ? (BK + 4) : (BM + 8);
    constexpr int B_PITCH = B_NK ? (BK + 4) : (BN + 8);
    constexpr int A_WORDS = A_MK ? BM * (BK + 4) : BK * (BM + 8);
    constexpr int B_WORDS = B_NK ? BN * (BK + 4) : BK * (BN + 8);
    __shared__ uint32_t sA[A_WORDS];
    __shared__ uint32_t sB[B_WORDS];

    const int z  = blockIdx.z;
    const int zo = z / innerCount;
    const int zi = z - zo * innerCount;
    const float* A = Ag + (long long)zo * aOut + (long long)zi * aIn;
    const float* B = Bg + (long long)zo * bOut + (long long)zi * bIn;
    float*       C = Cg + (long long)zo * cOut + (long long)zi * cIn;

    const int m0g = blockIdx.y * BM;
    const int n0g = blockIdx.x * BN;
    const int tid  = threadIdx.x;
    const int warp = tid >> 5;
    const int lane = tid & 31;
    const int wm = warp & 3;
    const int wn = warp >> 2;
    const int g  = lane >> 2;
    const int tg = lane & 3;

    float acc[2][8][4];
    #pragma unroll
    for (int mi = 0; mi < 2; mi++)
        #pragma unroll
        for (int ni = 0; ni < 8; ni++)
            #pragma unroll
            for (int q = 0; q < 4; q++) acc[mi][ni][q] = 0.f;

    for (int k0g = 0; k0g < K; k0g += BK) {
        if constexpr (!A_MK) {
            #pragma unroll
            for (int j = 0; j < 4; j++) {
                int idx = tid + j * 256;
                int k = idx >> 5, m = (idx & 31) << 2;
                float4 v = *reinterpret_cast<const float4*>(&A[(long long)(k0g + k) * lda + m0g + m]);
                uint4 w = make_uint4(f2tf(v.x), f2tf(v.y), f2tf(v.z), f2tf(v.w));
                *reinterpret_cast<uint4*>(&sA[k * A_PITCH + m]) = w;
            }
        } else {
            #pragma unroll
            for (int j = 0; j < 4; j++) {
                int idx = tid + j * 256;
                int m = idx >> 3, k = (idx & 7) << 2;
                float4 v = *reinterpret_cast<const float4*>(&A[(long long)(m0g + m) * lda + k0g + k]);
                uint4 w = make_uint4(f2tf(v.x), f2tf(v.y), f2tf(v.z), f2tf(v.w));
                *reinterpret_cast<uint4*>(&sA[m * A_PITCH + k]) = w;
            }
        }
        if constexpr (!B_NK) {
            #pragma unroll
            for (int j = 0; j < 4; j++) {
                int idx = tid + j * 256;
                int k = idx >> 5, n = (idx & 31) << 2;
                float4 v = *reinterpret_cast<const float4*>(&B[(long long)(k0g + k) * ldb + n0g + n]);
                uint4 w = make_uint4(f2tf(v.x), f2tf(v.y), f2tf(v.z), f2tf(v.w));
                *reinterpret_cast<uint4*>(&sB[k * B_PITCH + n]) = w;
            }
        } else {
            #pragma unroll
            for (int j = 0; j < 4; j++) {
                int idx = tid + j * 256;
                int n = idx >> 3, k = (idx & 7) << 2;
                float4 v = *reinterpret_cast<const float4*>(&B[(long long)(n0g + n) * ldb + k0g + k]);
                uint4 w = make_uint4(f2tf(v.x), f2tf(v.y), f2tf(v.z), f2tf(v.w));
                *reinterpret_cast<uint4*>(&sB[n * B_PITCH + k]) = w;
            }
        }
        __syncthreads();

        #pragma unroll
        for (int ks = 0; ks < BK / 8; ks++) {
            const int k0 = ks * 8;
            uint32_t af[2][4], bf[8][2];
            #pragma unroll
            for (int mi = 0; mi < 2; mi++) {
                const int rb = wm * 32 + mi * 16;
                if constexpr (A_MK) {
                    af[mi][0] = sA[(rb + g)     * A_PITCH + k0 + tg];
                    af[mi][1] = sA[(rb + 8 + g) * A_PITCH + k0 + tg];
                    af[mi][2] = sA[(rb + g)     * A_PITCH + k0 + 4 + tg];
                    af[mi][3] = sA[(rb + 8 + g) * A_PITCH + k0 + 4 + tg];
                } else {
                    af[mi][0] = sA[(k0 + tg)     * A_PITCH + rb + g];
                    af[mi][1] = sA[(k0 + tg)     * A_PITCH + rb + 8 + g];
                    af[mi][2] = sA[(k0 + 4 + tg) * A_PITCH + rb + g];
                    af[mi][3] = sA[(k0 + 4 + tg) * A_PITCH + rb + 8 + g];
                }
            }
            #pragma unroll
            for (int ni = 0; ni < 8; ni++) {
                const int cb = wn * 64 + ni * 8 + g;
                if constexpr (B_NK) {
                    bf[ni][0] = sB[cb * B_PITCH + k0 + tg];
                    bf[ni][1] = sB[cb * B_PITCH + k0 + 4 + tg];
                } else {
                    bf[ni][0] = sB[(k0 + tg)     * B_PITCH + cb];
                    bf[ni][1] = sB[(k0 + 4 + tg) * B_PITCH + cb];
                }
            }
            #pragma unroll
            for (int mi = 0; mi < 2; mi++)
                #pragma unroll
                for (int ni = 0; ni < 8; ni++)
                    asm volatile(
                        "mma.sync.aligned.m16n8k8.row.col.f32.tf32.tf32.f32 "
                        "{%0,%1,%2,%3}, {%4,%5,%6,%7}, {%8,%9}, {%0,%1,%2,%3};\n"
                        : "+f"(acc[mi][ni][0]), "+f"(acc[mi][ni][1]),
                          "+f"(acc[mi][ni][2]), "+f"(acc[mi][ni][3])
                        : "r"(af[mi][0]), "r"(af[mi][1]), "r"(af[mi][2]), "r"(af[mi][3]),
                          "r"(bf[ni][0]), "r"(bf[ni][1]));
        }
        __syncthreads();
    }

    #pragma unroll
    for (int mi = 0; mi < 2; mi++) {
        const int r0 = m0g + wm * 32 + mi * 16 + g;
        #pragma unroll
        for (int ni = 0; ni < 8; ni++) {
            const int c0 = n0g + wn * 64 + ni * 8 + tg * 2;
            float2 v0 = make_float2(acc[mi][ni][0], acc[mi][ni][1]);
            float2 v1 = make_float2(acc[mi][ni][2], acc[mi][ni][3]);
            if constexpr (ROUND_OUT) {
                v0.x = __uint_as_float(f2tf(v0.x)); v0.y = __uint_as_float(f2tf(v0.y));
                v1.x = __uint_as_float(f2tf(v1.x)); v1.y = __uint_as_float(f2tf(v1.y));
            }
            *reinterpret_cast<float2*>(&C[(long long)r0 * ldc + c0]) = v0;
            *reinterpret_cast<float2*>(&C[(long long)(r0 + 8) * ldc + c0]) = v1;
        }
    }
}

// ---------------- big GEMM: out(4096x8192) = Z @ Wr^T + bias (x) S ----------------
// CTA tile 128x256, BK=32, 8 warps (2M x 4N), warp tile 64x64, 3-stage cp.async.
#define TM 128
#define TN 256
#define TK 32
#define NST 3
#define KT 64                               // 2048 / 32
#define APITCH 36
#define BPITCH 36
#define A_WORDS (TM * APITCH)               // 4608
#define B_WORDS (TN * BPITCH)               // 9216
#define STG_WORDS (A_WORDS + B_WORDS)       // 13824
#define BIG_SMEM (NST * STG_WORDS * 4)      // 165888 bytes

__device__ __forceinline__ void cp16(uint32_t dst, const float* src) {
    asm volatile("cp.async.cg.shared.global [%0], [%1], 16;" :: "r"(dst), "l"(src));
}

__global__ void __launch_bounds__(256) big_gemm(
    const float* __restrict__ Z, const float* __restrict__ W,
    const float* __restrict__ bias, const float* __restrict__ S,
    float* __restrict__ out)
{
    extern __shared__ uint32_t smem[];
    uint32_t sbase;
    asm("{ .reg .u64 t; cvta.to.shared.u64 t, %1; cvt.u32.u64 %0, t; }"
        : "=r"(sbase) : "l"(smem));

    const int tid  = threadIdx.x;
    const int warp = tid >> 5;
    const int lane = tid & 31;
    const int wm = warp & 1;        // 2 warps along M (64 rows each)
    const int wn = warp >> 1;       // 4 warps along N (64 cols each)
    const int g  = lane >> 2;
    const int tg = lane & 3;

    const int m0 = blockIdx.x * TM;      // x fastest: wave = all M-tiles x few N-tiles
    const int n0 = blockIdx.y * TN;
    const float* Ab = Z + (size_t)m0 * 2048;
    const float* Bb = W + (size_t)n0 * 2048;

    float acc[4][8][4];
    #pragma unroll
    for (int mi = 0; mi < 4; mi++)
        #pragma unroll
        for (int ni = 0; ni < 8; ni++)
            #pragma unroll
            for (int q = 0; q < 4; q++) acc[mi][ni][q] = 0.f;

    auto load_tile = [&](int stg, int kt) {
        const uint32_t sA = sbase + (uint32_t)stg * (STG_WORDS * 4);
        const uint32_t sB = sA + A_WORDS * 4;
        const float* As = Ab + kt * TK;
        const float* Bs = Bb + kt * TK;
        #pragma unroll
        for (int j = 0; j < 4; j++) {            // A: 1024 chunks
            int idx = tid + j * 256;
            int r = idx >> 3, c = idx & 7;
            cp16(sA + (uint32_t)(r * (APITCH * 4) + c * 16), As + (size_t)r * 2048 + c * 4);
        }
        #pragma unroll
        for (int j = 0; j < 8; j++) {            // B: 2048 chunks
            int idx = tid + j * 256;
            int r = idx >> 3, c = idx & 7;
            cp16(sB + (uint32_t)(r * (BPITCH * 4) + c * 16), Bs + (size_t)r * 2048 + c * 4);
        }
        asm volatile("cp.async.commit_group;" ::: "memory");
    };

    // prologue: stages 0,1
    load_tile(0, 0);
    load_tile(1, 1);

    for (int kt = 0; kt < KT; kt++) {
        if (kt == KT - 1) asm volatile("cp.async.wait_group 0;" ::: "memory");
        else              asm volatile("cp.async.wait_group 1;" ::: "memory");
        __syncthreads();

        // prefetch tile kt+2 into buffer (kt+2)%3
        if (kt + 2 < KT) load_tile((kt + 2) % NST, kt + 2);

        const uint32_t* sA = smem + (size_t)(kt % NST) * STG_WORDS;
        const uint32_t* sB = sA + A_WORDS;

        #pragma unroll
        for (int ks = 0; ks < 4; ks++) {
            const int k0 = ks * 8;
            uint32_t af[4][4], bf[8][2];
            #pragma unroll
            for (int mi = 0; mi < 4; mi++) {
                const int rb = wm * 64 + mi * 16;
                af[mi][0] = sA[(rb + g)     * APITCH + k0 + tg];
                af[mi][1] = sA[(rb + 8 + g) * APITCH + k0 + tg];
                af[mi][2] = sA[(rb + g)     * APITCH + k0 + 4 + tg];
                af[mi][3] = sA[(rb + 8 + g) * APITCH + k0 + 4 + tg];
            }
            #pragma unroll
            for (int ni = 0; ni < 8; ni++) {
                const int cb = wn * 64 + ni * 8 + g;
                bf[ni][0] = sB[cb * BPITCH + k0 + tg];
                bf[ni][1] = sB[cb * BPITCH + k0 + 4 + tg];
            }
            #pragma unroll
            for (int mi = 0; mi < 4; mi++)
                #pragma unroll
                for (int ni = 0; ni < 8; ni++)
                    asm volatile(
                        "mma.sync.aligned.m16n8k8.row.col.f32.tf32.tf32.f32 "
                        "{%0,%1,%2,%3}, {%4,%5,%6,%7}, {%8,%9}, {%0,%1,%2,%3};\n"
                        : "+f"(acc[mi][ni][0]), "+f"(acc[mi][ni][1]),
                          "+f"(acc[mi][ni][2]), "+f"(acc[mi][ni][3])
                        : "r"(af[mi][0]), "r"(af[mi][1]), "r"(af[mi][2]), "r"(af[mi][3]),
                          "r"(bf[ni][0]), "r"(bf[ni][1]));
        }
        __syncthreads();
    }

    // epilogue: out = acc + bias[n] * S[m]
    #pragma unroll
    for (int mi = 0; mi < 4; mi++) {
        const int r0 = m0 + wm * 64 + mi * 16 + g;
        const float s0 = S[r0], s1 = S[r0 + 8];
        #pragma unroll
        for (int ni = 0; ni < 8; ni++) {
            const int c0 = n0 + wn * 64 + ni * 8 + tg * 2;
            const float b0 = bias[c0], b1 = bias[c0 + 1];
            float2 v0 = make_float2(acc[mi][ni][0] + b0 * s0, acc[mi][ni][1] + b1 * s0);
            float2 v1 = make_float2(acc[mi][ni][2] + b0 * s1, acc[mi][ni][3] + b1 * s1);
            *reinterpret_cast<float2*>(&out[(size_t)r0 * 8192 + c0]) = v0;
            *reinterpret_cast<float2*>(&out[(size_t)(r0 + 8) * 8192 + c0]) = v1;
        }
    }
}

// ---------------- launch ----------------
extern "C" void kernel_launch(void* const* d_in, const int* in_sizes, int n_in,
                              void* d_out, int out_size)
{
    const float* x      = (const float*)d_in[0];  // (4,1024,2048)
    const float* cmb    = (const float*)d_in[1];  // (4,1024,4,512)
    const float* mask   = (const float*)d_in[2];  // (4,1024,4,512)
    const float* weight = (const float*)d_in[3];  // (8192,2048)
    const float* bias   = (const float*)d_in[4];  // (8192,)
    float* out = (float*)d_out;                   // (4,1024,8192)

    float *Xd, *Z, *Wr, *S;
    cudaGetSymbolAddress((void**)&Xd, g_Xd);
    cudaGetSymbolAddress((void**)&Z,  g_Z);
    cudaGetSymbolAddress((void**)&Wr, g_Wr);
    cudaGetSymbolAddress((void**)&S,  g_S);

    combine_rowsum<<<512, 256>>>(cmb, S);
    permute_round_w<<<16384, 256>>>(weight, Wr);

    // Stage 1: Xd[b,e](512x512) = mask^T @ x-slice
    {
        dim3 grid(512 / BN, 512 / BM, 16);
        gemm_tf32<false, false, false><<<grid, 256>>>(
            mask, x, Xd, 1024, 2048, 2048, 512,
            2097152LL, 512LL, 2097152LL, 512LL,
            1048576LL, 262144LL, 4);
    }
    // Stage 2: Z[b,:,e*512:](1024x512) = cmb[b,:,e,:] @ Xd[b,e]   (tf32-rounded output)
    {
        dim3 grid(512 / BN, 1024 / BM, 16);
        gemm_tf32<true, false, true><<<grid, 256>>>(
            cmb, Xd, Z, 512, 2048, 512, 2048,
            2097152LL, 512LL, 1048576LL, 262144LL,
            2097152LL, 512LL, 4);
    }
    // Stage 3: out = Z(4096x2048) @ Wr^T(2048x8192) + bias (x) S
    {
        cudaFuncSetAttribute(big_gemm, cudaFuncAttributeMaxDynamicSharedMemorySize, BIG_SMEM);
        dim3 grid(4096 / TM, 8192 / TN, 1);
        big_gemm<<<grid, 256, BIG_SMEM>>>(Z, Wr, bias, S, out);
    }
}

// round 7
// speedup vs baseline: 2.4773x; 1.6454x over previous
#include <cuda_runtime.h>
#include <cuda_fp16.h>
#include <cstdint>
#include <cstddef>

// Problem: B=4, T=1024, E=4, C=512, i=512, IN=2048, OUT=8192
//   w[e,o,j] = weight_flat[e*4194304 + o*512 + j]   (torch-style reshape)
//   Xd[b,e] = mask[b,:,e,:]^T @ x[b,:,e*512:]        (tf32 SIMT)
//   Zh[b,:,e*512:] = cmb[b,:,e,:] @ Xd[b,e]          (tf32 SIMT, half output)
//   out[b] = Zh[b] @ Wh^T + bias (x) rowsum(cmb)     (fp16 MMA, M=4096,N=8192,K=2048)

// ---------------- scratch (allocation-free rule) ----------------
static __device__ float  g_Xd[4ull * 4 * 512 * 512];   // 16 MB
static __device__ __half g_Zh[4096ull * 2048];         // 16 MB
static __device__ __half g_Wh[8192ull * 2048];         // 32 MB (permuted half weight)
static __device__ float  g_S [4 * 1024];

__device__ __forceinline__ uint32_t f2tf(float f) {
    uint32_t u;
    asm("cvt.rna.tf32.f32 %0, %1;" : "=r"(u) : "f"(f));
    return u;
}

// ---------------- tiny kernels ----------------
__global__ void combine_rowsum(const float* __restrict__ cmb, float* __restrict__ S) {
    int row = blockIdx.x * (blockDim.x >> 5) + (threadIdx.x >> 5);
    int lane = threadIdx.x & 31;
    const float4* p = reinterpret_cast<const float4*>(cmb + (size_t)row * 2048);
    float s = 0.f;
    #pragma unroll 4
    for (int j = lane; j < 512; j += 32) {
        float4 v = p[j];
        s += (v.x + v.y) + (v.z + v.w);
    }
    #pragma unroll
    for (int o = 16; o; o >>= 1) s += __shfl_xor_sync(0xffffffffu, s, o);
    if (lane == 0) S[row] = s;
}

// Wh[o, e*512 + j] = half(weight_flat[e*4194304 + o*512 + j])
__global__ void permute_w_h(const float* __restrict__ in, __half* __restrict__ out) {
    size_t idx = (size_t)blockIdx.x * blockDim.x + threadIdx.x;  // 4,194,304 threads
    int j4 = (int)(idx & 127);
    int o  = (int)((idx >> 7) & 8191);
    int e  = (int)(idx >> 20);
    float4 v = *reinterpret_cast<const float4*>(in + (size_t)e * 4194304 + (size_t)o * 512 + j4 * 4);
    __half2 h01 = __floats2half2_rn(v.x, v.y);
    __half2 h23 = __floats2half2_rn(v.z, v.w);
    uint2 w;
    w.x = *reinterpret_cast<uint32_t*>(&h01);
    w.y = *reinterpret_cast<uint32_t*>(&h23);
    *reinterpret_cast<uint2*>(out + (size_t)o * 2048 + e * 512 + j4 * 4) = w;
}

// ---------------- SIMT tf32 GEMM (stages 1 & 2) ----------------
#define BM 128
#define BN 128
#define BK 32

template <bool A_MK, bool B_NK, bool OUT_HALF>
__global__ void __launch_bounds__(256, 2) gemm_tf32(
    const float* __restrict__ Ag, const float* __restrict__ Bg, void* __restrict__ Cg,
    int K, long long lda, long long ldb, long long ldc,
    long long aOut, long long aIn, long long bOut, long long bIn,
    long long cOut, long long cIn, int innerCount)
{
    constexpr int A_PITCH = A_MK ? (BK + 4) : (BM + 8);
    constexpr int B_PITCH = B_NK ? (BK + 4) : (BN + 8);
    constexpr int A_WORDS = A_MK ? BM * (BK + 4) : BK * (BM + 8);
    constexpr int B_WORDS = B_NK ? BN * (BK + 4) : BK * (BN + 8);
    __shared__ uint32_t sA[A_WORDS];
    __shared__ uint32_t sB[B_WORDS];

    const int z  = blockIdx.z;
    const int zo = z / innerCount;
    const int zi = z - zo * innerCount;
    const float* A = Ag + (long long)zo * aOut + (long long)zi * aIn;
    const float* B = Bg + (long long)zo * bOut + (long long)zi * bIn;

    const int m0g = blockIdx.y * BM;
    const int n0g = blockIdx.x * BN;
    const int tid  = threadIdx.x;
    const int warp = tid >> 5;
    const int lane = tid & 31;
    const int wm = warp & 3;
    const int wn = warp >> 2;
    const int g  = lane >> 2;
    const int tg = lane & 3;

    float acc[2][8][4];
    #pragma unroll
    for (int mi = 0; mi < 2; mi++)
        #pragma unroll
        for (int ni = 0; ni < 8; ni++)
            #pragma unroll
            for (int q = 0; q < 4; q++) acc[mi][ni][q] = 0.f;

    for (int k0g = 0; k0g < K; k0g += BK) {
        if constexpr (!A_MK) {
            #pragma unroll
            for (int j = 0; j < 4; j++) {
                int idx = tid + j * 256;
                int k = idx >> 5, m = (idx & 31) << 2;
                float4 v = *reinterpret_cast<const float4*>(&A[(long long)(k0g + k) * lda + m0g + m]);
                uint4 w = make_uint4(f2tf(v.x), f2tf(v.y), f2tf(v.z), f2tf(v.w));
                *reinterpret_cast<uint4*>(&sA[k * A_PITCH + m]) = w;
            }
        } else {
            #pragma unroll
            for (int j = 0; j < 4; j++) {
                int idx = tid + j * 256;
                int m = idx >> 3, k = (idx & 7) << 2;
                float4 v = *reinterpret_cast<const float4*>(&A[(long long)(m0g + m) * lda + k0g + k]);
                uint4 w = make_uint4(f2tf(v.x), f2tf(v.y), f2tf(v.z), f2tf(v.w));
                *reinterpret_cast<uint4*>(&sA[m * A_PITCH + k]) = w;
            }
        }
        if constexpr (!B_NK) {
            #pragma unroll
            for (int j = 0; j < 4; j++) {
                int idx = tid + j * 256;
                int k = idx >> 5, n = (idx & 31) << 2;
                float4 v = *reinterpret_cast<const float4*>(&B[(long long)(k0g + k) * ldb + n0g + n]);
                uint4 w = make_uint4(f2tf(v.x), f2tf(v.y), f2tf(v.z), f2tf(v.w));
                *reinterpret_cast<uint4*>(&sB[k * B_PITCH + n]) = w;
            }
        } else {
            #pragma unroll
            for (int j = 0; j < 4; j++) {
                int idx = tid + j * 256;
                int n = idx >> 3, k = (idx & 7) << 2;
                float4 v = *reinterpret_cast<const float4*>(&B[(long long)(n0g + n) * ldb + k0g + k]);
                uint4 w = make_uint4(f2tf(v.x), f2tf(v.y), f2tf(v.z), f2tf(v.w));
                *reinterpret_cast<uint4*>(&sB[n * B_PITCH + k]) = w;
            }
        }
        __syncthreads();

        #pragma unroll
        for (int ks = 0; ks < BK / 8; ks++) {
            const int k0 = ks * 8;
            uint32_t af[2][4], bf[8][2];
            #pragma unroll
            for (int mi = 0; mi < 2; mi++) {
                const int rb = wm * 32 + mi * 16;
                if constexpr (A_MK) {
                    af[mi][0] = sA[(rb + g)     * A_PITCH + k0 + tg];
                    af[mi][1] = sA[(rb + 8 + g) * A_PITCH + k0 + tg];
                    af[mi][2] = sA[(rb + g)     * A_PITCH + k0 + 4 + tg];
                    af[mi][3] = sA[(rb + 8 + g) * A_PITCH + k0 + 4 + tg];
                } else {
                    af[mi][0] = sA[(k0 + tg)     * A_PITCH + rb + g];
                    af[mi][1] = sA[(k0 + tg)     * A_PITCH + rb + 8 + g];
                    af[mi][2] = sA[(k0 + 4 + tg) * A_PITCH + rb + g];
                    af[mi][3] = sA[(k0 + 4 + tg) * A_PITCH + rb + 8 + g];
                }
            }
            #pragma unroll
            for (int ni = 0; ni < 8; ni++) {
                const int cb = wn * 64 + ni * 8 + g;
                if constexpr (B_NK) {
                    bf[ni][0] = sB[cb * B_PITCH + k0 + tg];
                    bf[ni][1] = sB[cb * B_PITCH + k0 + 4 + tg];
                } else {
                    bf[ni][0] = sB[(k0 + tg)     * B_PITCH + cb];
                    bf[ni][1] = sB[(k0 + 4 + tg) * B_PITCH + cb];
                }
            }
            #pragma unroll
            for (int mi = 0; mi < 2; mi++)
                #pragma unroll
                for (int ni = 0; ni < 8; ni++)
                    asm volatile(
                        "mma.sync.aligned.m16n8k8.row.col.f32.tf32.tf32.f32 "
                        "{%0,%1,%2,%3}, {%4,%5,%6,%7}, {%8,%9}, {%0,%1,%2,%3};\n"
                        : "+f"(acc[mi][ni][0]), "+f"(acc[mi][ni][1]),
                          "+f"(acc[mi][ni][2]), "+f"(acc[mi][ni][3])
                        : "r"(af[mi][0]), "r"(af[mi][1]), "r"(af[mi][2]), "r"(af[mi][3]),
                          "r"(bf[ni][0]), "r"(bf[ni][1]));
        }
        __syncthreads();
    }

    #pragma unroll
    for (int mi = 0; mi < 2; mi++) {
        const int r0 = m0g + wm * 32 + mi * 16 + g;
        #pragma unroll
        for (int ni = 0; ni < 8; ni++) {
            const int c0 = n0g + wn * 64 + ni * 8 + tg * 2;
            if constexpr (OUT_HALF) {
                __half* C = (__half*)Cg + (long long)zo * cOut + (long long)zi * cIn;
                __half2 h0 = __floats2half2_rn(acc[mi][ni][0], acc[mi][ni][1]);
                __half2 h1 = __floats2half2_rn(acc[mi][ni][2], acc[mi][ni][3]);
                *reinterpret_cast<__half2*>(&C[(long long)r0 * ldc + c0]) = h0;
                *reinterpret_cast<__half2*>(&C[(long long)(r0 + 8) * ldc + c0]) = h1;
            } else {
                float* C = (float*)Cg + (long long)zo * cOut + (long long)zi * cIn;
                float2 v0 = make_float2(acc[mi][ni][0], acc[mi][ni][1]);
                float2 v1 = make_float2(acc[mi][ni][2], acc[mi][ni][3]);
                *reinterpret_cast<float2*>(&C[(long long)r0 * ldc + c0]) = v0;
                *reinterpret_cast<float2*>(&C[(long long)(r0 + 8) * ldc + c0]) = v1;
            }
        }
    }
}

// ---------------- big GEMM (fp16): out(4096x8192) = Zh @ Wh^T + bias (x) S ----------------
// CTA tile 128x256, BK=64 halves, 8 warps (2M x 4N), warp tile 64x64, 3-stage cp.async.
#define TM 128
#define TN 256
#define HBK 64
#define NST 3
#define HKT 32                              // 2048 / 64
#define HPITCH 36                           // uint32 per row = 72 halves (64 + 8 pad; 144B ≡ 16 mod 128)
#define A_WORDS (TM * HPITCH)               // 4608 u32
#define B_WORDS (TN * HPITCH)               // 9216 u32
#define STG_WORDS (A_WORDS + B_WORDS)       // 13824 u32
#define BIG_SMEM (NST * STG_WORDS * 4)      // 165888 bytes

__device__ __forceinline__ void cp16(uint32_t dst, const void* src) {
    asm volatile("cp.async.cg.shared.global [%0], [%1], 16;" :: "r"(dst), "l"(src));
}

__global__ void __launch_bounds__(256) big_gemm_h(
    const __half* __restrict__ Z, const __half* __restrict__ W,
    const float* __restrict__ bias, const float* __restrict__ S,
    float* __restrict__ out)
{
    extern __shared__ uint32_t smem[];
    uint32_t sbase;
    asm("{ .reg .u64 t; cvta.to.shared.u64 t, %1; cvt.u32.u64 %0, t; }"
        : "=r"(sbase) : "l"(smem));

    const int tid  = threadIdx.x;
    const int warp = tid >> 5;
    const int lane = tid & 31;
    const int wm = warp & 1;        // 2 warps along M (64 rows each)
    const int wn = warp >> 1;       // 4 warps along N (64 cols each)
    const int g  = lane >> 2;
    const int tg = lane & 3;

    const int m0 = blockIdx.x * TM;      // x fastest: wave = all M-tiles x few N-tiles
    const int n0 = blockIdx.y * TN;
    const __half* Ab = Z + (size_t)m0 * 2048;
    const __half* Bb = W + (size_t)n0 * 2048;

    float acc[4][8][4];
    #pragma unroll
    for (int mi = 0; mi < 4; mi++)
        #pragma unroll
        for (int ni = 0; ni < 8; ni++)
            #pragma unroll
            for (int q = 0; q < 4; q++) acc[mi][ni][q] = 0.f;

    auto load_tile = [&](int stg, int kt) {
        const uint32_t sA = sbase + (uint32_t)stg * (STG_WORDS * 4);
        const uint32_t sB = sA + A_WORDS * 4;
        const __half* As = Ab + kt * HBK;
        const __half* Bs = Bb + kt * HBK;
        #pragma unroll
        for (int j = 0; j < 4; j++) {            // A: 128 rows x 8 chunks = 1024
            int idx = tid + j * 256;
            int r = idx >> 3, c = idx & 7;
            cp16(sA + (uint32_t)(r * (HPITCH * 4) + c * 16), As + (size_t)r * 2048 + c * 8);
        }
        #pragma unroll
        for (int j = 0; j < 8; j++) {            // B: 256 rows x 8 chunks = 2048
            int idx = tid + j * 256;
            int r = idx >> 3, c = idx & 7;
            cp16(sB + (uint32_t)(r * (HPITCH * 4) + c * 16), Bs + (size_t)r * 2048 + c * 8);
        }
        asm volatile("cp.async.commit_group;" ::: "memory");
    };

    // prologue: stages 0,1
    load_tile(0, 0);
    load_tile(1, 1);

    for (int kt = 0; kt < HKT; kt++) {
        if (kt == HKT - 1) asm volatile("cp.async.wait_group 0;" ::: "memory");
        else               asm volatile("cp.async.wait_group 1;" ::: "memory");
        __syncthreads();

        if (kt + 2 < HKT) load_tile((kt + 2) % NST, kt + 2);

        const uint32_t* sA = smem + (size_t)(kt % NST) * STG_WORDS;
        const uint32_t* sB = sA + A_WORDS;

        #pragma unroll
        for (int ks = 0; ks < 4; ks++) {           // 4 x k16 per tile
            const int k0 = ks * 8;                 // uint32 offset: k16 halves = 8 u32
            uint32_t af[4][4], bf[8][2];
            #pragma unroll
            for (int mi = 0; mi < 4; mi++) {
                const int rb = wm * 64 + mi * 16;
                af[mi][0] = sA[(rb + g)     * HPITCH + k0 + tg];      // (m=g,   k=tg*2..+1)
                af[mi][1] = sA[(rb + 8 + g) * HPITCH + k0 + tg];      // (m=g+8, k=tg*2..+1)
                af[mi][2] = sA[(rb + g)     * HPITCH + k0 + 4 + tg];  // (m=g,   k=tg*2+8..+9)
                af[mi][3] = sA[(rb + 8 + g) * HPITCH + k0 + 4 + tg];  // (m=g+8, k=tg*2+8..+9)
            }
            #pragma unroll
            for (int ni = 0; ni < 8; ni++) {
                const int cb = wn * 64 + ni * 8 + g;
                bf[ni][0] = sB[cb * HPITCH + k0 + tg];
                bf[ni][1] = sB[cb * HPITCH + k0 + 4 + tg];
            }
            #pragma unroll
            for (int mi = 0; mi < 4; mi++)
                #pragma unroll
                for (int ni = 0; ni < 8; ni++)
                    asm volatile(
                        "mma.sync.aligned.m16n8k16.row.col.f32.f16.f16.f32 "
                        "{%0,%1,%2,%3}, {%4,%5,%6,%7}, {%8,%9}, {%0,%1,%2,%3};\n"
                        : "+f"(acc[mi][ni][0]), "+f"(acc[mi][ni][1]),
                          "+f"(acc[mi][ni][2]), "+f"(acc[mi][ni][3])
                        : "r"(af[mi][0]), "r"(af[mi][1]), "r"(af[mi][2]), "r"(af[mi][3]),
                          "r"(bf[ni][0]), "r"(bf[ni][1]));
        }
        __syncthreads();
    }

    // epilogue: out = acc + bias[n] * S[m]
    #pragma unroll
    for (int mi = 0; mi < 4; mi++) {
        const int r0 = m0 + wm * 64 + mi * 16 + g;
        const float s0 = S[r0], s1 = S[r0 + 8];
        #pragma unroll
        for (int ni = 0; ni < 8; ni++) {
            const int c0 = n0 + wn * 64 + ni * 8 + tg * 2;
            const float b0 = bias[c0], b1 = bias[c0 + 1];
            float2 v0 = make_float2(acc[mi][ni][0] + b0 * s0, acc[mi][ni][1] + b1 * s0);
            float2 v1 = make_float2(acc[mi][ni][2] + b0 * s1, acc[mi][ni][3] + b1 * s1);
            *reinterpret_cast<float2*>(&out[(size_t)r0 * 8192 + c0]) = v0;
            *reinterpret_cast<float2*>(&out[(size_t)(r0 + 8) * 8192 + c0]) = v1;
        }
    }
}

// ---------------- launch ----------------
extern "C" void kernel_launch(void* const* d_in, const int* in_sizes, int n_in,
                              void* d_out, int out_size)
{
    const float* x      = (const float*)d_in[0];  // (4,1024,2048)
    const float* cmb    = (const float*)d_in[1];  // (4,1024,4,512)
    const float* mask   = (const float*)d_in[2];  // (4,1024,4,512)
    const float* weight = (const float*)d_in[3];  // (8192,2048)
    const float* bias   = (const float*)d_in[4];  // (8192,)
    float* out = (float*)d_out;                   // (4,1024,8192)

    float *Xd, *S;
    __half *Zh, *Wh;
    cudaGetSymbolAddress((void**)&Xd, g_Xd);
    cudaGetSymbolAddress((void**)&Zh, g_Zh);
    cudaGetSymbolAddress((void**)&Wh, g_Wh);
    cudaGetSymbolAddress((void**)&S,  g_S);

    combine_rowsum<<<512, 256>>>(cmb, S);
    permute_w_h<<<16384, 256>>>(weight, Wh);

    // Stage 1: Xd[b,e](512x512) = mask^T @ x-slice   (fp32 out)
    {
        dim3 grid(512 / BN, 512 / BM, 16);
        gemm_tf32<false, false, false><<<grid, 256>>>(
            mask, x, Xd, 1024, 2048, 2048, 512,
            2097152LL, 512LL, 2097152LL, 512LL,
            1048576LL, 262144LL, 4);
    }
    // Stage 2: Zh[b,:,e*512:](1024x512) = cmb[b,:,e,:] @ Xd[b,e]   (half out)
    {
        dim3 grid(512 / BN, 1024 / BM, 16);
        gemm_tf32<true, false, true><<<grid, 256>>>(
            cmb, Xd, Zh, 512, 2048, 512, 2048,
            2097152LL, 512LL, 1048576LL, 262144LL,
            2097152LL, 512LL, 4);
    }
    // Stage 3: out = Zh(4096x2048) @ Wh^T(2048x8192) + bias (x) S   (fp16 MMA)
    {
        cudaFuncSetAttribute(big_gemm_h, cudaFuncAttributeMaxDynamicSharedMemorySize, BIG_SMEM);
        dim3 grid(4096 / TM, 8192 / TN, 1);
        big_gemm_h<<<grid, 256, BIG_SMEM>>>(Zh, Wh, bias, S, out);
    }
}

// round 8
// speedup vs baseline: 2.5898x; 1.0454x over previous
#include <cuda_runtime.h>
#include <cuda_fp16.h>
#include <cstdint>
#include <cstddef>

// Problem: B=4, T=1024, E=4, C=512, i=512, IN=2048, OUT=8192
//   w[e,o,j] = weight_flat[e*4194304 + o*512 + j]   (torch-style reshape)
//   Xd[b,e] = mask[b,:,e,:]^T @ x[b,:,e*512:]        (tf32 SIMT)
//   Zh[b,:,e*512:] = cmb[b,:,e,:] @ Xd[b,e]          (tf32 SIMT, half output)
//   out[b] = Zh[b] @ Wh^T + bias (x) rowsum(cmb)     (fp16 MMA, M=4096,N=8192,K=2048)

// ---------------- scratch (allocation-free rule) ----------------
static __device__ float  g_Xd[4ull * 4 * 512 * 512];   // 16 MB
static __device__ __half g_Zh[4096ull * 2048];         // 16 MB
static __device__ __half g_Wh[8192ull * 2048];         // 32 MB (permuted half weight)
static __device__ float  g_S [4 * 1024];

__device__ __forceinline__ uint32_t f2tf(float f) {
    uint32_t u;
    asm("cvt.rna.tf32.f32 %0, %1;" : "=r"(u) : "f"(f));
    return u;
}

// ---------------- tiny kernels ----------------
__global__ void combine_rowsum(const float* __restrict__ cmb, float* __restrict__ S) {
    int row = blockIdx.x * (blockDim.x >> 5) + (threadIdx.x >> 5);
    int lane = threadIdx.x & 31;
    const float4* p = reinterpret_cast<const float4*>(cmb + (size_t)row * 2048);
    float s = 0.f;
    #pragma unroll 4
    for (int j = lane; j < 512; j += 32) {
        float4 v = p[j];
        s += (v.x + v.y) + (v.z + v.w);
    }
    #pragma unroll
    for (int o = 16; o; o >>= 1) s += __shfl_xor_sync(0xffffffffu, s, o);
    if (lane == 0) S[row] = s;
}

// Wh[o, e*512 + j] = half(weight_flat[e*4194304 + o*512 + j])
__global__ void permute_w_h(const float* __restrict__ in, __half* __restrict__ out) {
    size_t idx = (size_t)blockIdx.x * blockDim.x + threadIdx.x;  // 4,194,304 threads
    int j4 = (int)(idx & 127);
    int o  = (int)((idx >> 7) & 8191);
    int e  = (int)(idx >> 20);
    float4 v = *reinterpret_cast<const float4*>(in + (size_t)e * 4194304 + (size_t)o * 512 + j4 * 4);
    __half2 h01 = __floats2half2_rn(v.x, v.y);
    __half2 h23 = __floats2half2_rn(v.z, v.w);
    uint2 w;
    w.x = *reinterpret_cast<uint32_t*>(&h01);
    w.y = *reinterpret_cast<uint32_t*>(&h23);
    *reinterpret_cast<uint2*>(out + (size_t)o * 2048 + e * 512 + j4 * 4) = w;
}

// ---------------- SIMT tf32 GEMM (stages 1 & 2) ----------------
#define BM 128
#define BN 128
#define BK 32

template <bool A_MK, bool B_NK, bool OUT_HALF>
__global__ void __launch_bounds__(256, 2) gemm_tf32(
    const float* __restrict__ Ag, const float* __restrict__ Bg, void* __restrict__ Cg,
    int K, long long lda, long long ldb, long long ldc,
    long long aOut, long long aIn, long long bOut, long long bIn,
    long long cOut, long long cIn, int innerCount)
{
    constexpr int A_PITCH = A_MK ? (BK + 4) : (BM + 8);
    constexpr int B_PITCH = B_NK ? (BK + 4) : (BN + 8);
    constexpr int A_WORDS = A_MK ? BM * (BK + 4) : BK * (BM + 8);
    constexpr int B_WORDS = B_NK ? BN * (BK + 4) : BK * (BN + 8);
    __shared__ uint32_t sA[A_WORDS];
    __shared__ uint32_t sB[B_WORDS];

    const int z  = blockIdx.z;
    const int zo = z / innerCount;
    const int zi = z - zo * innerCount;
    const float* A = Ag + (long long)zo * aOut + (long long)zi * aIn;
    const float* B = Bg + (long long)zo * bOut + (long long)zi * bIn;

    const int m0g = blockIdx.y * BM;
    const int n0g = blockIdx.x * BN;
    const int tid  = threadIdx.x;
    const int warp = tid >> 5;
    const int lane = tid & 31;
    const int wm = warp & 3;
    const int wn = warp >> 2;
    const int g  = lane >> 2;
    const int tg = lane & 3;

    float acc[2][8][4];
    #pragma unroll
    for (int mi = 0; mi < 2; mi++)
        #pragma unroll
        for (int ni = 0; ni < 8; ni++)
            #pragma unroll
            for (int q = 0; q < 4; q++) acc[mi][ni][q] = 0.f;

    for (int k0g = 0; k0g < K; k0g += BK) {
        if constexpr (!A_MK) {
            #pragma unroll
            for (int j = 0; j < 4; j++) {
                int idx = tid + j * 256;
                int k = idx >> 5, m = (idx & 31) << 2;
                float4 v = *reinterpret_cast<const float4*>(&A[(long long)(k0g + k) * lda + m0g + m]);
                uint4 w = make_uint4(f2tf(v.x), f2tf(v.y), f2tf(v.z), f2tf(v.w));
                *reinterpret_cast<uint4*>(&sA[k * A_PITCH + m]) = w;
            }
        } else {
            #pragma unroll
            for (int j = 0; j < 4; j++) {
                int idx = tid + j * 256;
                int m = idx >> 3, k = (idx & 7) << 2;
                float4 v = *reinterpret_cast<const float4*>(&A[(long long)(m0g + m) * lda + k0g + k]);
                uint4 w = make_uint4(f2tf(v.x), f2tf(v.y), f2tf(v.z), f2tf(v.w));
                *reinterpret_cast<uint4*>(&sA[m * A_PITCH + k]) = w;
            }
        }
        if constexpr (!B_NK) {
            #pragma unroll
            for (int j = 0; j < 4; j++) {
                int idx = tid + j * 256;
                int k = idx >> 5, n = (idx & 31) << 2;
                float4 v = *reinterpret_cast<const float4*>(&B[(long long)(k0g + k) * ldb + n0g + n]);
                uint4 w = make_uint4(f2tf(v.x), f2tf(v.y), f2tf(v.z), f2tf(v.w));
                *reinterpret_cast<uint4*>(&sB[k * B_PITCH + n]) = w;
            }
        } else {
            #pragma unroll
            for (int j = 0; j < 4; j++) {
                int idx = tid + j * 256;
                int n = idx >> 3, k = (idx & 7) << 2;
                float4 v = *reinterpret_cast<const float4*>(&B[(long long)(n0g + n) * ldb + k0g + k]);
                uint4 w = make_uint4(f2tf(v.x), f2tf(v.y), f2tf(v.z), f2tf(v.w));
                *reinterpret_cast<uint4*>(&sB[n * B_PITCH + k]) = w;
            }
        }
        __syncthreads();

        #pragma unroll
        for (int ks = 0; ks < BK / 8; ks++) {
            const int k0 = ks * 8;
            uint32_t af[2][4], bf[8][2];
            #pragma unroll
            for (int mi = 0; mi < 2; mi++) {
                const int rb = wm * 32 + mi * 16;
                if constexpr (A_MK) {
                    af[mi][0] = sA[(rb + g)     * A_PITCH + k0 + tg];
                    af[mi][1] = sA[(rb + 8 + g) * A_PITCH + k0 + tg];
                    af[mi][2] = sA[(rb + g)     * A_PITCH + k0 + 4 + tg];
                    af[mi][3] = sA[(rb + 8 + g) * A_PITCH + k0 + 4 + tg];
                } else {
                    af[mi][0] = sA[(k0 + tg)     * A_PITCH + rb + g];
                    af[mi][1] = sA[(k0 + tg)     * A_PITCH + rb + 8 + g];
                    af[mi][2] = sA[(k0 + 4 + tg) * A_PITCH + rb + g];
                    af[mi][3] = sA[(k0 + 4 + tg) * A_PITCH + rb + 8 + g];
                }
            }
            #pragma unroll
            for (int ni = 0; ni < 8; ni++) {
                const int cb = wn * 64 + ni * 8 + g;
                if constexpr (B_NK) {
                    bf[ni][0] = sB[cb * B_PITCH + k0 + tg];
                    bf[ni][1] = sB[cb * B_PITCH + k0 + 4 + tg];
                } else {
                    bf[ni][0] = sB[(k0 + tg)     * B_PITCH + cb];
                    bf[ni][1] = sB[(k0 + 4 + tg) * B_PITCH + cb];
                }
            }
            #pragma unroll
            for (int mi = 0; mi < 2; mi++)
                #pragma unroll
                for (int ni = 0; ni < 8; ni++)
                    asm volatile(
                        "mma.sync.aligned.m16n8k8.row.col.f32.tf32.tf32.f32 "
                        "{%0,%1,%2,%3}, {%4,%5,%6,%7}, {%8,%9}, {%0,%1,%2,%3};\n"
                        : "+f"(acc[mi][ni][0]), "+f"(acc[mi][ni][1]),
                          "+f"(acc[mi][ni][2]), "+f"(acc[mi][ni][3])
                        : "r"(af[mi][0]), "r"(af[mi][1]), "r"(af[mi][2]), "r"(af[mi][3]),
                          "r"(bf[ni][0]), "r"(bf[ni][1]));
        }
        __syncthreads();
    }

    #pragma unroll
    for (int mi = 0; mi < 2; mi++) {
        const int r0 = m0g + wm * 32 + mi * 16 + g;
        #pragma unroll
        for (int ni = 0; ni < 8; ni++) {
            const int c0 = n0g + wn * 64 + ni * 8 + tg * 2;
            if constexpr (OUT_HALF) {
                __half* C = (__half*)Cg + (long long)zo * cOut + (long long)zi * cIn;
                __half2 h0 = __floats2half2_rn(acc[mi][ni][0], acc[mi][ni][1]);
                __half2 h1 = __floats2half2_rn(acc[mi][ni][2], acc[mi][ni][3]);
                *reinterpret_cast<__half2*>(&C[(long long)r0 * ldc + c0]) = h0;
                *reinterpret_cast<__half2*>(&C[(long long)(r0 + 8) * ldc + c0]) = h1;
            } else {
                float* C = (float*)Cg + (long long)zo * cOut + (long long)zi * cIn;
                float2 v0 = make_float2(acc[mi][ni][0], acc[mi][ni][1]);
                float2 v1 = make_float2(acc[mi][ni][2], acc[mi][ni][3]);
                *reinterpret_cast<float2*>(&C[(long long)r0 * ldc + c0]) = v0;
                *reinterpret_cast<float2*>(&C[(long long)(r0 + 8) * ldc + c0]) = v1;
            }
        }
    }
}

// ---------------- big GEMM (fp16 + LDSM): out = Zh @ Wh^T + bias (x) S ----------------
// CTA 128x256, BK=64 halves, 8 warps (2M x 4N), warp tile 64x64, 4-stage cp.async,
// single __syncthreads per tile, ldmatrix.x4 fragment loads.
#define TM 128
#define TN 256
#define HBK 64
#define NST 4
#define HKT 32                              // 2048 / 64
#define HPITCH 36                           // u32 per row (72 halves; 144B pitch -> LDSM conflict-free)
#define A_WORDS (TM * HPITCH)               // 4608 u32
#define B_WORDS (TN * HPITCH)               // 9216 u32
#define STG_WORDS (A_WORDS + B_WORDS)       // 13824 u32
#define BIG_SMEM (NST * STG_WORDS * 4)      // 221184 bytes

__device__ __forceinline__ void cp16(uint32_t dst, const void* src) {
    asm volatile("cp.async.cg.shared.global [%0], [%1], 16;" :: "r"(dst), "l"(src));
}

__global__ void __launch_bounds__(256) big_gemm_h(
    const __half* __restrict__ Z, const __half* __restrict__ W,
    const float* __restrict__ bias, const float* __restrict__ S,
    float* __restrict__ out)
{
    extern __shared__ uint32_t smem[];
    uint32_t sbase;
    asm("{ .reg .u64 t; cvta.to.shared.u64 t, %1; cvt.u32.u64 %0, t; }"
        : "=r"(sbase) : "l"(smem));

    const int tid  = threadIdx.x;
    const int warp = tid >> 5;
    const int lane = tid & 31;
    const int wm = warp & 1;        // 2 warps along M (64 rows each)
    const int wn = warp >> 1;       // 4 warps along N (64 cols each)
    const int g  = lane >> 2;
    const int tg = lane & 3;

    const int m0 = blockIdx.x * TM;      // x fastest: wave = all M-tiles x few N-tiles
    const int n0 = blockIdx.y * TN;
    const __half* Ab = Z + (size_t)m0 * 2048;
    const __half* Bb = W + (size_t)n0 * 2048;

    // ldmatrix per-lane row/col components (byte offsets within tile)
    const uint32_t aRow = (uint32_t)((lane & 7) + (lane & 8));          // + rb
    const uint32_t aCol = (uint32_t)((lane >> 4) << 4);                 // + kbyte
    const uint32_t bRow = (uint32_t)((lane & 7) + ((lane >> 4) << 3));  // + cb0
    const uint32_t bCol = (uint32_t)((lane & 8) << 1);                  // + kbyte

    float acc[4][8][4];
    #pragma unroll
    for (int mi = 0; mi < 4; mi++)
        #pragma unroll
        for (int ni = 0; ni < 8; ni++)
            #pragma unroll
            for (int q = 0; q < 4; q++) acc[mi][ni][q] = 0.f;

    auto load_tile = [&](int stg, int kt) {
        const uint32_t sA = sbase + (uint32_t)stg * (STG_WORDS * 4);
        const uint32_t sB = sA + A_WORDS * 4;
        const __half* As = Ab + kt * HBK;
        const __half* Bs = Bb + kt * HBK;
        #pragma unroll
        for (int j = 0; j < 4; j++) {            // A: 128 rows x 8 chunks = 1024
            int idx = tid + j * 256;
            int r = idx >> 3, c = idx & 7;
            cp16(sA + (uint32_t)(r * (HPITCH * 4) + c * 16), As + (size_t)r * 2048 + c * 8);
        }
        #pragma unroll
        for (int j = 0; j < 8; j++) {            // B: 256 rows x 8 chunks = 2048
            int idx = tid + j * 256;
            int r = idx >> 3, c = idx & 7;
            cp16(sB + (uint32_t)(r * (HPITCH * 4) + c * 16), Bs + (size_t)r * 2048 + c * 8);
        }
    };

    // prologue: tiles 0..2 into bufs 0..2
    #pragma unroll
    for (int s = 0; s < NST - 1; s++) {
        load_tile(s, s);
        asm volatile("cp.async.commit_group;" ::: "memory");
    }

    for (int kt = 0; kt < HKT; kt++) {
        // commits so far = 3 + kt; wait<=2 in flight => tiles 0..kt landed
        asm volatile("cp.async.wait_group 2;" ::: "memory");
        __syncthreads();   // also orders last tile's consumption before refilling its buffer

        if (kt + NST - 1 < HKT) load_tile((kt + NST - 1) & (NST - 1), kt + NST - 1);
        asm volatile("cp.async.commit_group;" ::: "memory");  // may be empty; keeps count uniform

        const uint32_t sAb = sbase + (uint32_t)((kt & (NST - 1)) * (STG_WORDS * 4));
        const uint32_t sBb = sAb + A_WORDS * 4;

        #pragma unroll
        for (int ks = 0; ks < 4; ks++) {           // 4 x k16 per tile
            const uint32_t kbyte = (uint32_t)(ks * 32);
            uint32_t af[4][4], bf[8][2];
            #pragma unroll
            for (int mi = 0; mi < 4; mi++) {
                const uint32_t addr = sAb + (uint32_t)(wm * 64 + mi * 16 + aRow) * (HPITCH * 4)
                                    + kbyte + aCol;
                asm volatile("ldmatrix.sync.aligned.m8n8.x4.shared.b16 {%0,%1,%2,%3}, [%4];"
                             : "=r"(af[mi][0]), "=r"(af[mi][1]), "=r"(af[mi][2]), "=r"(af[mi][3])
                             : "r"(addr));
            }
            #pragma unroll
            for (int np = 0; np < 4; np++) {       // covers ni = 2*np, 2*np+1
                const uint32_t addr = sBb + (uint32_t)(wn * 64 + np * 16 + bRow) * (HPITCH * 4)
                                    + kbyte + bCol;
                asm volatile("ldmatrix.sync.aligned.m8n8.x4.shared.b16 {%0,%1,%2,%3}, [%4];"
                             : "=r"(bf[2 * np][0]), "=r"(bf[2 * np][1]),
                               "=r"(bf[2 * np + 1][0]), "=r"(bf[2 * np + 1][1])
                             : "r"(addr));
            }
            #pragma unroll
            for (int mi = 0; mi < 4; mi++)
                #pragma unroll
                for (int ni = 0; ni < 8; ni++)
                    asm volatile(
                        "mma.sync.aligned.m16n8k16.row.col.f32.f16.f16.f32 "
                        "{%0,%1,%2,%3}, {%4,%5,%6,%7}, {%8,%9}, {%0,%1,%2,%3};\n"
                        : "+f"(acc[mi][ni][0]), "+f"(acc[mi][ni][1]),
                          "+f"(acc[mi][ni][2]), "+f"(acc[mi][ni][3])
                        : "r"(af[mi][0]), "r"(af[mi][1]), "r"(af[mi][2]), "r"(af[mi][3]),
                          "r"(bf[ni][0]), "r"(bf[ni][1]));
        }
    }

    // epilogue: out = acc + bias[n] * S[m]
    #pragma unroll
    for (int mi = 0; mi < 4; mi++) {
        const int r0 = m0 + wm * 64 + mi * 16 + g;
        const float s0 = S[r0], s1 = S[r0 + 8];
        #pragma unroll
        for (int ni = 0; ni < 8; ni++) {
            const int c0 = n0 + wn * 64 + ni * 8 + tg * 2;
            const float b0 = bias[c0], b1 = bias[c0 + 1];
            float2 v0 = make_float2(acc[mi][ni][0] + b0 * s0, acc[mi][ni][1] + b1 * s0);
            float2 v1 = make_float2(acc[mi][ni][2] + b0 * s1, acc[mi][ni][3] + b1 * s1);
            *reinterpret_cast<float2*>(&out[(size_t)r0 * 8192 + c0]) = v0;
            *reinterpret_cast<float2*>(&out[(size_t)(r0 + 8) * 8192 + c0]) = v1;
        }
    }
}

// ---------------- launch ----------------
extern "C" void kernel_launch(void* const* d_in, const int* in_sizes, int n_in,
                              void* d_out, int out_size)
{
    const float* x      = (const float*)d_in[0];  // (4,1024,2048)
    const float* cmb    = (const float*)d_in[1];  // (4,1024,4,512)
    const float* mask   = (const float*)d_in[2];  // (4,1024,4,512)
    const float* weight = (const float*)d_in[3];  // (8192,2048)
    const float* bias   = (const float*)d_in[4];  // (8192,)
    float* out = (float*)d_out;                   // (4,1024,8192)

    float *Xd, *S;
    __half *Zh, *Wh;
    cudaGetSymbolAddress((void**)&Xd, g_Xd);
    cudaGetSymbolAddress((void**)&Zh, g_Zh);
    cudaGetSymbolAddress((void**)&Wh, g_Wh);
    cudaGetSymbolAddress((void**)&S,  g_S);

    combine_rowsum<<<512, 256>>>(cmb, S);
    permute_w_h<<<16384, 256>>>(weight, Wh);

    // Stage 1: Xd[b,e](512x512) = mask^T @ x-slice   (fp32 out)
    {
        dim3 grid(512 / BN, 512 / BM, 16);
        gemm_tf32<false, false, false><<<grid, 256>>>(
            mask, x, Xd, 1024, 2048, 2048, 512,
            2097152LL, 512LL, 2097152LL, 512LL,
            1048576LL, 262144LL, 4);
    }
    // Stage 2: Zh[b,:,e*512:](1024x512) = cmb[b,:,e,:] @ Xd[b,e]   (half out)
    {
        dim3 grid(512 / BN, 1024 / BM, 16);
        gemm_tf32<true, false, true><<<grid, 256>>>(
            cmb, Xd, Zh, 512, 2048, 512, 2048,
            2097152LL, 512LL, 1048576LL, 262144LL,
            2097152LL, 512LL, 4);
    }
    // Stage 3: out = Zh(4096x2048) @ Wh^T(2048x8192) + bias (x) S   (fp16 MMA + LDSM)
    {
        cudaFuncSetAttribute(big_gemm_h, cudaFuncAttributeMaxDynamicSharedMemorySize, BIG_SMEM);
        dim3 grid(4096 / TM, 8192 / TN, 1);
        big_gemm_h<<<grid, 256, BIG_SMEM>>>(Zh, Wh, bias, S, out);
    }
}

// round 9
// speedup vs baseline: 2.8111x; 1.0854x over previous
#include <cuda_runtime.h>
#include <cuda_fp16.h>
#include <cstdint>
#include <cstddef>

// Problem: B=4, T=1024, E=4, C=512, i=512, IN=2048, OUT=8192
//   w[e,o,j] = weight_flat[e*4194304 + o*512 + j]   (torch-style reshape)
//   Xd[b,e] = mask[b,:,e,:]^T @ x[b,:,e*512:]        (fp16 MMA, half out)
//   Zh[b,:,e*512:] = cmb[b,:,e,:] @ Xd[b,e]          (fp16 MMA, half out)
//   out[b] = Zh[b] @ Wh^T + bias (x) rowsum(cmb)     (fp16 MMA, M=4096,N=8192,K=2048)

// ---------------- scratch (allocation-free rule) ----------------
static __device__ __half g_Xd[4ull * 4 * 512 * 512];   // 8 MB (half)
static __device__ __half g_Zh[4096ull * 2048];         // 16 MB
static __device__ __half g_Wh[8192ull * 2048];         // 32 MB (permuted half weight)
static __device__ float  g_S [4 * 1024];

// ---------------- tiny kernels ----------------
__global__ void combine_rowsum(const float* __restrict__ cmb, float* __restrict__ S) {
    int row = blockIdx.x * (blockDim.x >> 5) + (threadIdx.x >> 5);
    int lane = threadIdx.x & 31;
    const float4* p = reinterpret_cast<const float4*>(cmb + (size_t)row * 2048);
    float s = 0.f;
    #pragma unroll 4
    for (int j = lane; j < 512; j += 32) {
        float4 v = p[j];
        s += (v.x + v.y) + (v.z + v.w);
    }
    #pragma unroll
    for (int o = 16; o; o >>= 1) s += __shfl_xor_sync(0xffffffffu, s, o);
    if (lane == 0) S[row] = s;
}

// Wh[o, e*512 + j] = half(weight_flat[e*4194304 + o*512 + j])
__global__ void permute_w_h(const float* __restrict__ in, __half* __restrict__ out) {
    size_t idx = (size_t)blockIdx.x * blockDim.x + threadIdx.x;  // 4,194,304 threads
    int j4 = (int)(idx & 127);
    int o  = (int)((idx >> 7) & 8191);
    int e  = (int)(idx >> 20);
    float4 v = *reinterpret_cast<const float4*>(in + (size_t)e * 4194304 + (size_t)o * 512 + j4 * 4);
    __half2 h01 = __floats2half2_rn(v.x, v.y);
    __half2 h23 = __floats2half2_rn(v.z, v.w);
    uint2 w;
    w.x = *reinterpret_cast<uint32_t*>(&h01);
    w.y = *reinterpret_cast<uint32_t*>(&h23);
    *reinterpret_cast<uint2*>(out + (size_t)o * 2048 + e * 512 + j4 * 4) = w;
}

__device__ __forceinline__ uint2 f4_to_h4(float4 v) {
    __half2 h01 = __floats2half2_rn(v.x, v.y);
    __half2 h23 = __floats2half2_rn(v.z, v.w);
    uint2 w;
    w.x = *reinterpret_cast<uint32_t*>(&h01);
    w.y = *reinterpret_cast<uint32_t*>(&h23);
    return w;
}

// ---------------- fp16 SIMT GEMM (stages 1 & 2) ----------------
// C[M,N](half) = A @ B, tiles 128x128xBK32 halves, 8 warps (4M x 2N), warp tile 32x64.
//   A_MK=true : A fp32 (m,k) k-contig  -> smem (m, k-pairs) pitch 20 u32, direct LDS frags
//   A_MK=false: A fp32 (k,m) m-contig  -> smem (k, m)       pitch 68 u32, ldmatrix.trans
//   B_HALF    : B half (k,n) n-contig  (else fp32 (k,n))    -> smem (k, n) pitch 68 u32, ldmatrix.trans
#define SBK 32
#define APK 20      // u32 pitch, A (m,k-pair) layout
#define AKM 68      // u32 pitch, A (k,m) layout (136 halves)
#define BKN 68      // u32 pitch, B (k,n) layout

template <bool A_MK, bool B_HALF>
__global__ void __launch_bounds__(256, 2) gemm_h16(
    const void* __restrict__ Ag, const void* __restrict__ Bg, __half* __restrict__ Cg,
    int K, long long lda, long long ldb, long long ldc,
    long long aOut, long long aIn, long long bOut, long long bIn,
    long long cOut, long long cIn, int innerCount)
{
    constexpr int A_WORDS = A_MK ? 128 * APK : SBK * AKM;
    __shared__ uint32_t sA[A_WORDS];
    __shared__ uint32_t sB[SBK * BKN];

    uint32_t sAb, sBb;
    asm("{ .reg .u64 t; cvta.to.shared.u64 t, %1; cvt.u32.u64 %0, t; }" : "=r"(sAb) : "l"(sA));
    asm("{ .reg .u64 t; cvta.to.shared.u64 t, %1; cvt.u32.u64 %0, t; }" : "=r"(sBb) : "l"(sB));

    const int z  = blockIdx.z;
    const int zo = z / innerCount;
    const int zi = z - zo * innerCount;

    const int m0g = blockIdx.y * 128;
    const int n0g = blockIdx.x * 128;
    const int tid  = threadIdx.x;
    const int warp = tid >> 5;
    const int lane = tid & 31;
    const int wm = warp & 3;        // 4 warps along M, 32 rows each
    const int wn = warp >> 2;       // 2 warps along N, 64 cols each
    const int g  = lane >> 2;
    const int tg = lane & 3;

    float acc[2][8][4];
    #pragma unroll
    for (int mi = 0; mi < 2; mi++)
        #pragma unroll
        for (int ni = 0; ni < 8; ni++)
            #pragma unroll
            for (int q = 0; q < 4; q++) acc[mi][ni][q] = 0.f;

    for (int k0g = 0; k0g < K; k0g += SBK) {
        // ---- A -> smem ----
        if constexpr (A_MK) {          // fp32 (m,k) k-contig: 128x32 = 1024 float4
            const float* A = (const float*)Ag + (long long)zo * aOut + (long long)zi * aIn;
            #pragma unroll
            for (int j = 0; j < 4; j++) {
                int idx = tid + j * 256;
                int m = idx >> 3, k4 = idx & 7;
                float4 v = *reinterpret_cast<const float4*>(&A[(long long)(m0g + m) * lda + k0g + k4 * 4]);
                *reinterpret_cast<uint2*>(&sA[m * APK + k4 * 2]) = f4_to_h4(v);
            }
        } else {                       // fp32 (k,m) m-contig: 32x128 = 1024 float4
            const float* A = (const float*)Ag + (long long)zo * aOut + (long long)zi * aIn;
            #pragma unroll
            for (int j = 0; j < 4; j++) {
                int idx = tid + j * 256;
                int k = idx >> 5, m4 = idx & 31;
                float4 v = *reinterpret_cast<const float4*>(&A[(long long)(k0g + k) * lda + m0g + m4 * 4]);
                *reinterpret_cast<uint2*>(&sA[k * AKM + m4 * 2]) = f4_to_h4(v);
            }
        }
        // ---- B -> smem ----
        if constexpr (B_HALF) {        // half (k,n) n-contig: 32x128 halves = 512 uint4
            const __half* B = (const __half*)Bg + (long long)zo * bOut + (long long)zi * bIn;
            #pragma unroll
            for (int j = 0; j < 2; j++) {
                int idx = tid + j * 256;
                int k = idx >> 4, n8 = idx & 15;
                uint4 v = *reinterpret_cast<const uint4*>(&B[(long long)(k0g + k) * ldb + n0g + n8 * 8]);
                *reinterpret_cast<uint4*>(&sB[k * BKN + n8 * 4]) = v;
            }
        } else {                       // fp32 (k,n) n-contig: 1024 float4
            const float* B = (const float*)Bg + (long long)zo * bOut + (long long)zi * bIn;
            #pragma unroll
            for (int j = 0; j < 4; j++) {
                int idx = tid + j * 256;
                int k = idx >> 5, n4 = idx & 31;
                float4 v = *reinterpret_cast<const float4*>(&B[(long long)(k0g + k) * ldb + n0g + n4 * 4]);
                *reinterpret_cast<uint2*>(&sB[k * BKN + n4 * 2]) = f4_to_h4(v);
            }
        }
        __syncthreads();

        #pragma unroll
        for (int ks = 0; ks < 2; ks++) {       // 2 x k16
            uint32_t af[2][4], bf[8][2];
            #pragma unroll
            for (int mi = 0; mi < 2; mi++) {
                const int rb = wm * 32 + mi * 16;
                if constexpr (A_MK) {
                    af[mi][0] = sA[(rb + g)     * APK + ks * 8 + tg];
                    af[mi][1] = sA[(rb + 8 + g) * APK + ks * 8 + tg];
                    af[mi][2] = sA[(rb + g)     * APK + ks * 8 + 4 + tg];
                    af[mi][3] = sA[(rb + 8 + g) * APK + ks * 8 + 4 + tg];
                } else {
                    // ldmatrix.x4.trans from (k,m): t0=(m0-7,k0-7) t1=(m8-15,k0-7) t2=(m,k8-15) t3
                    const uint32_t row = (uint32_t)(ks * 16 + (lane & 7) + (((lane >> 4) & 1) << 3));
                    const uint32_t col = (uint32_t)(rb + (((lane >> 3) & 1) << 3));
                    const uint32_t addr = sAb + row * (AKM * 4) + col * 2;
                    asm volatile("ldmatrix.sync.aligned.m8n8.x4.trans.shared.b16 {%0,%1,%2,%3}, [%4];"
                                 : "=r"(af[mi][0]), "=r"(af[mi][1]), "=r"(af[mi][2]), "=r"(af[mi][3])
                                 : "r"(addr));
                }
            }
            #pragma unroll
            for (int np = 0; np < 4; np++) {   // each x4 covers ni = 2np, 2np+1
                // t0=(k0-7,n0-7) t1=(k8-15,n0-7) t2=(k0-7,n8-15) t3=(k8-15,n8-15)
                const uint32_t row = (uint32_t)(ks * 16 + (lane & 7) + (((lane >> 3) & 1) << 3));
                const uint32_t col = (uint32_t)(wn * 64 + np * 16 + (((lane >> 4) & 1) << 3));
                const uint32_t addr = sBb + row * (BKN * 4) + col * 2;
                asm volatile("ldmatrix.sync.aligned.m8n8.x4.trans.shared.b16 {%0,%1,%2,%3}, [%4];"
                             : "=r"(bf[2 * np][0]), "=r"(bf[2 * np][1]),
                               "=r"(bf[2 * np + 1][0]), "=r"(bf[2 * np + 1][1])
                             : "r"(addr));
            }
            #pragma unroll
            for (int mi = 0; mi < 2; mi++)
                #pragma unroll
                for (int ni = 0; ni < 8; ni++)
                    asm volatile(
                        "mma.sync.aligned.m16n8k16.row.col.f32.f16.f16.f32 "
                        "{%0,%1,%2,%3}, {%4,%5,%6,%7}, {%8,%9}, {%0,%1,%2,%3};\n"
                        : "+f"(acc[mi][ni][0]), "+f"(acc[mi][ni][1]),
                          "+f"(acc[mi][ni][2]), "+f"(acc[mi][ni][3])
                        : "r"(af[mi][0]), "r"(af[mi][1]), "r"(af[mi][2]), "r"(af[mi][3]),
                          "r"(bf[ni][0]), "r"(bf[ni][1]));
        }
        __syncthreads();
    }

    __half* C = Cg + (long long)zo * cOut + (long long)zi * cIn;
    #pragma unroll
    for (int mi = 0; mi < 2; mi++) {
        const int r0 = m0g + wm * 32 + mi * 16 + g;
        #pragma unroll
        for (int ni = 0; ni < 8; ni++) {
            const int c0 = n0g + wn * 64 + ni * 8 + tg * 2;
            __half2 h0 = __floats2half2_rn(acc[mi][ni][0], acc[mi][ni][1]);
            __half2 h1 = __floats2half2_rn(acc[mi][ni][2], acc[mi][ni][3]);
            *reinterpret_cast<__half2*>(&C[(long long)r0 * ldc + c0]) = h0;
            *reinterpret_cast<__half2*>(&C[(long long)(r0 + 8) * ldc + c0]) = h1;
        }
    }
}

// ---------------- big GEMM (fp16 + LDSM): out = Zh @ Wh^T + bias (x) S ----------------
// CTA 128x256, BK=64 halves, 8 warps (2M x 4N), warp tile 64x64, 4-stage cp.async,
// single __syncthreads per tile, ldmatrix.x4 fragment loads.
#define TM 128
#define TN 256
#define HBK 64
#define NST 4
#define HKT 32                              // 2048 / 64
#define HPITCH 36                           // u32 per row (72 halves; 144B pitch -> LDSM conflict-free)
#define A_WORDS (TM * HPITCH)               // 4608 u32
#define B_WORDS (TN * HPITCH)               // 9216 u32
#define STG_WORDS (A_WORDS + B_WORDS)       // 13824 u32
#define BIG_SMEM (NST * STG_WORDS * 4)      // 221184 bytes

__device__ __forceinline__ void cp16(uint32_t dst, const void* src) {
    asm volatile("cp.async.cg.shared.global [%0], [%1], 16;" :: "r"(dst), "l"(src));
}

__global__ void __launch_bounds__(256) big_gemm_h(
    const __half* __restrict__ Z, const __half* __restrict__ W,
    const float* __restrict__ bias, const float* __restrict__ S,
    float* __restrict__ out)
{
    extern __shared__ uint32_t smem[];
    uint32_t sbase;
    asm("{ .reg .u64 t; cvta.to.shared.u64 t, %1; cvt.u32.u64 %0, t; }"
        : "=r"(sbase) : "l"(smem));

    const int tid  = threadIdx.x;
    const int warp = tid >> 5;
    const int lane = tid & 31;
    const int wm = warp & 1;        // 2 warps along M (64 rows each)
    const int wn = warp >> 1;       // 4 warps along N (64 cols each)
    const int g  = lane >> 2;
    const int tg = lane & 3;

    const int m0 = blockIdx.x * TM;      // x fastest: wave = all M-tiles x few N-tiles
    const int n0 = blockIdx.y * TN;
    const __half* Ab = Z + (size_t)m0 * 2048;
    const __half* Bb = W + (size_t)n0 * 2048;

    // ldmatrix per-lane row/col components (byte offsets within tile)
    const uint32_t aRow = (uint32_t)((lane & 7) + (lane & 8));          // + rb
    const uint32_t aCol = (uint32_t)((lane >> 4) << 4);                 // + kbyte
    const uint32_t bRow = (uint32_t)((lane & 7) + ((lane >> 4) << 3));  // + cb0
    const uint32_t bCol = (uint32_t)((lane & 8) << 1);                  // + kbyte

    float acc[4][8][4];
    #pragma unroll
    for (int mi = 0; mi < 4; mi++)
        #pragma unroll
        for (int ni = 0; ni < 8; ni++)
            #pragma unroll
            for (int q = 0; q < 4; q++) acc[mi][ni][q] = 0.f;

    auto load_tile = [&](int stg, int kt) {
        const uint32_t sA = sbase + (uint32_t)stg * (STG_WORDS * 4);
        const uint32_t sB = sA + A_WORDS * 4;
        const __half* As = Ab + kt * HBK;
        const __half* Bs = Bb + kt * HBK;
        #pragma unroll
        for (int j = 0; j < 4; j++) {            // A: 128 rows x 8 chunks = 1024
            int idx = tid + j * 256;
            int r = idx >> 3, c = idx & 7;
            cp16(sA + (uint32_t)(r * (HPITCH * 4) + c * 16), As + (size_t)r * 2048 + c * 8);
        }
        #pragma unroll
        for (int j = 0; j < 8; j++) {            // B: 256 rows x 8 chunks = 2048
            int idx = tid + j * 256;
            int r = idx >> 3, c = idx & 7;
            cp16(sB + (uint32_t)(r * (HPITCH * 4) + c * 16), Bs + (size_t)r * 2048 + c * 8);
        }
    };

    // prologue: tiles 0..2 into bufs 0..2
    #pragma unroll
    for (int s = 0; s < NST - 1; s++) {
        load_tile(s, s);
        asm volatile("cp.async.commit_group;" ::: "memory");
    }

    for (int kt = 0; kt < HKT; kt++) {
        asm volatile("cp.async.wait_group 2;" ::: "memory");
        __syncthreads();

        if (kt + NST - 1 < HKT) load_tile((kt + NST - 1) & (NST - 1), kt + NST - 1);
        asm volatile("cp.async.commit_group;" ::: "memory");

        const uint32_t sAb = sbase + (uint32_t)((kt & (NST - 1)) * (STG_WORDS * 4));
        const uint32_t sBb = sAb + A_WORDS * 4;

        #pragma unroll
        for (int ks = 0; ks < 4; ks++) {
            const uint32_t kbyte = (uint32_t)(ks * 32);
            uint32_t af[4][4], bf[8][2];
            #pragma unroll
            for (int mi = 0; mi < 4; mi++) {
                const uint32_t addr = sAb + (uint32_t)(wm * 64 + mi * 16 + aRow) * (HPITCH * 4)
                                    + kbyte + aCol;
                asm volatile("ldmatrix.sync.aligned.m8n8.x4.shared.b16 {%0,%1,%2,%3}, [%4];"
                             : "=r"(af[mi][0]), "=r"(af[mi][1]), "=r"(af[mi][2]), "=r"(af[mi][3])
                             : "r"(addr));
            }
            #pragma unroll
            for (int np = 0; np < 4; np++) {
                const uint32_t addr = sBb + (uint32_t)(wn * 64 + np * 16 + bRow) * (HPITCH * 4)
                                    + kbyte + bCol;
                asm volatile("ldmatrix.sync.aligned.m8n8.x4.shared.b16 {%0,%1,%2,%3}, [%4];"
                             : "=r"(bf[2 * np][0]), "=r"(bf[2 * np][1]),
                               "=r"(bf[2 * np + 1][0]), "=r"(bf[2 * np + 1][1])
                             : "r"(addr));
            }
            #pragma unroll
            for (int mi = 0; mi < 4; mi++)
                #pragma unroll
                for (int ni = 0; ni < 8; ni++)
                    asm volatile(
                        "mma.sync.aligned.m16n8k16.row.col.f32.f16.f16.f32 "
                        "{%0,%1,%2,%3}, {%4,%5,%6,%7}, {%8,%9}, {%0,%1,%2,%3};\n"
                        : "+f"(acc[mi][ni][0]), "+f"(acc[mi][ni][1]),
                          "+f"(acc[mi][ni][2]), "+f"(acc[mi][ni][3])
                        : "r"(af[mi][0]), "r"(af[mi][1]), "r"(af[mi][2]), "r"(af[mi][3]),
                          "r"(bf[ni][0]), "r"(bf[ni][1]));
        }
    }

    // epilogue: out = acc + bias[n] * S[m]
    #pragma unroll
    for (int mi = 0; mi < 4; mi++) {
        const int r0 = m0 + wm * 64 + mi * 16 + g;
        const float s0 = S[r0], s1 = S[r0 + 8];
        #pragma unroll
        for (int ni = 0; ni < 8; ni++) {
            const int c0 = n0 + wn * 64 + ni * 8 + tg * 2;
            const float b0 = bias[c0], b1 = bias[c0 + 1];
            float2 v0 = make_float2(acc[mi][ni][0] + b0 * s0, acc[mi][ni][1] + b1 * s0);
            float2 v1 = make_float2(acc[mi][ni][2] + b0 * s1, acc[mi][ni][3] + b1 * s1);
            *reinterpret_cast<float2*>(&out[(size_t)r0 * 8192 + c0]) = v0;
            *reinterpret_cast<float2*>(&out[(size_t)(r0 + 8) * 8192 + c0]) = v1;
        }
    }
}

// ---------------- launch ----------------
extern "C" void kernel_launch(void* const* d_in, const int* in_sizes, int n_in,
                              void* d_out, int out_size)
{
    const float* x      = (const float*)d_in[0];  // (4,1024,2048)
    const float* cmb    = (const float*)d_in[1];  // (4,1024,4,512)
    const float* mask   = (const float*)d_in[2];  // (4,1024,4,512)
    const float* weight = (const float*)d_in[3];  // (8192,2048)
    const float* bias   = (const float*)d_in[4];  // (8192,)
    float* out = (float*)d_out;                   // (4,1024,8192)

    float *S;
    __half *Xd, *Zh, *Wh;
    cudaGetSymbolAddress((void**)&Xd, g_Xd);
    cudaGetSymbolAddress((void**)&Zh, g_Zh);
    cudaGetSymbolAddress((void**)&Wh, g_Wh);
    cudaGetSymbolAddress((void**)&S,  g_S);

    combine_rowsum<<<512, 256>>>(cmb, S);
    permute_w_h<<<16384, 256>>>(weight, Wh);

    // Stage 1: Xd[b,e](512x512,half) = mask^T @ x-slice   (A fp32 (k,m), B fp32 (k,n))
    {
        dim3 grid(512 / 128, 512 / 128, 16);
        gemm_h16<false, false><<<grid, 256>>>(
            mask, x, Xd, 1024, 2048, 2048, 512,
            2097152LL, 512LL, 2097152LL, 512LL,
            1048576LL, 262144LL, 4);
    }
    // Stage 2: Zh[b,:,e*512:](1024x512) = cmb @ Xd[b,e]   (A fp32 (m,k), B half (k,n))
    {
        dim3 grid(512 / 128, 1024 / 128, 16);
        gemm_h16<true, true><<<grid, 256>>>(
            cmb, Xd, Zh, 512, 2048, 512, 2048,
            2097152LL, 512LL, 1048576LL, 262144LL,
            2097152LL, 512LL, 4);
    }
    // Stage 3: out = Zh(4096x2048) @ Wh^T(2048x8192) + bias (x) S   (fp16 MMA + LDSM)
    {
        cudaFuncSetAttribute(big_gemm_h, cudaFuncAttributeMaxDynamicSharedMemorySize, BIG_SMEM);
        dim3 grid(4096 / TM, 8192 / TN, 1);
        big_gemm_h<<<grid, 256, BIG_SMEM>>>(Zh, Wh, bias, S, out);
    }
}